// round 15
// baseline (speedup 1.0000x reference)
#include <cuda_runtime.h>

// Problem constants (fixed by the reference)
#define B_       4
#define L_       8192
#define D_       1024
#define K_       7
#define HALF_    3
#define THREADS_ 256      // one float4 (4 channels) per thread: 256*4 = D
#define ROWS_    54       // output rows per strip
#define STRIPS_  152      // ceil(8192/54); grid = 4*152 = 608
#define NSTREAM_ 60       // rows consumed per strip = ROWS_ + K_ - 1
#define PIPE_    10       // smem ring depth (rows); NSTREAM_ % PIPE_ == 0
#define AHEAD_   8        // prefetch distance (< PIPE_ for WAR gap)
#define ROWBYTES_ (THREADS_ * 16)   // 4096 B per ring stage

__global__ __launch_bounds__(THREADS_, 3)
void dwconv_pipe_kernel(const float* __restrict__ x,
                        const float* __restrict__ sb,
                        const float* __restrict__ w,     // (D,1,K) -> w[d*K + k]
                        const float* __restrict__ bias,  // (D,)
                        float* __restrict__ out)
{
    __shared__ __align__(16) float4 ring[PIPE_][THREADS_];
    __shared__ float mask_s[ROWS_];

    const int b  = blockIdx.x / STRIPS_;
    const int j  = blockIdx.x % STRIPS_;
    const int r0 = j * ROWS_;
    const int r1 = min(r0 + ROWS_, L_);
    const int t  = threadIdx.x;

    // ---- masks for strip rows: count boundaries in [l-3,l+3], mask = 2^-cnt
    if (t < ROWS_) {
        const int l = r0 + t;
        float m = 0.0f;
        if (l < L_) {
            float cnt = 0.0f;
            #pragma unroll
            for (int q = -HALF_; q <= HALF_; ++q) {
                const int p = l + q;
                if (p >= 0 && p < L_) cnt += __ldg(sb + b * L_ + p);
            }
            m = exp2f(-cnt);
        }
        mask_s[t] = m;
    }

    // ---- per-thread weights for channels d0..d0+3 (L2-resident)
    const int d0 = t << 2;
    float4 wk[K_];
    #pragma unroll
    for (int k = 0; k < K_; ++k) {
        wk[k].x = __ldg(w + (d0 + 0) * K_ + k);
        wk[k].y = __ldg(w + (d0 + 1) * K_ + k);
        wk[k].z = __ldg(w + (d0 + 2) * K_ + k);
        wk[k].w = __ldg(w + (d0 + 3) * K_ + k);
    }
    const float4 bs = *reinterpret_cast<const float4*>(bias + d0);

    const float* xb = x   + ((size_t)b * L_) * D_ + d0;
    float*       ob = out + ((size_t)b * L_) * D_ + d0;

    const int lr_first = r0 - (K_ - 1);

    const unsigned ring_base =
        (unsigned)__cvta_generic_to_shared(&ring[0][t]);

    // ---- prologue: issue AHEAD_ rows (stages 0..AHEAD_-1), one group each
    #pragma unroll
    for (int s = 0; s < AHEAD_; ++s) {
        const int lr = lr_first + s;
        const int lc = lr < 0 ? 0 : lr;          // clamp; garbage zeroed at use
        const float* src = xb + (size_t)lc * D_;
        asm volatile("cp.async.cg.shared.global [%0], [%1], 16;"
                     :: "r"(ring_base + s * ROWBYTES_), "l"(src));
        asm volatile("cp.async.commit_group;");
    }

    __syncthreads();   // mask_s ready (does not affect per-thread cp.async)

    float4 win[K_];    // filled during first K_-1 iterations (guarded compute)
    #pragma unroll
    for (int k = 0; k < K_; ++k) win[k] = make_float4(0.f, 0.f, 0.f, 0.f);

    #pragma unroll 1
    for (int io = 0; io < NSTREAM_ / PIPE_; ++io) {
        #pragma unroll
        for (int ii = 0; ii < PIPE_; ++ii) {
            const int i  = io * PIPE_ + ii;
            const int lr = lr_first + i;

            // issue prefetch for row i+AHEAD_ (stage (ii+AHEAD_)%PIPE_, static)
            {
                const int ip = i + AHEAD_;
                if (ip < NSTREAM_) {
                    int lrp = lr_first + ip;
                    int lc  = lrp < 0 ? 0 : (lrp >= L_ ? L_ - 1 : lrp);
                    const float* src = xb + (size_t)lc * D_;
                    asm volatile("cp.async.cg.shared.global [%0], [%1], 16;"
                                 :: "r"(ring_base +
                                        ((ii + AHEAD_) % PIPE_) * ROWBYTES_),
                                    "l"(src));
                }
                asm volatile("cp.async.commit_group;");
            }
            // row i complete when at most AHEAD_ groups pending
            asm volatile("cp.async.wait_group %0;" :: "n"(AHEAD_) : "memory");

            // consume row lr (thread reads back only its own 16 B)
            float4 v = ring[ii][t];
            if (lr < 0) v = make_float4(0.f, 0.f, 0.f, 0.f);

            // slide window: win = rows lr-6 .. lr
            #pragma unroll
            for (int k = 0; k < K_ - 1; ++k) win[k] = win[k + 1];
            win[K_ - 1] = v;

            if (lr >= r0 && lr < r1) {
                float4 acc = bs;
                #pragma unroll
                for (int k = 0; k < K_; ++k) {
                    acc.x = fmaf(win[k].x, wk[k].x, acc.x);
                    acc.y = fmaf(win[k].y, wk[k].y, acc.y);
                    acc.z = fmaf(win[k].z, wk[k].z, acc.z);
                    acc.w = fmaf(win[k].w, wk[k].w, acc.w);
                }
                const float m = mask_s[lr - r0];
                acc.x *= m; acc.y *= m; acc.z *= m; acc.w *= m;
                // write-through store: full coalesced 128B lines straight to
                // DRAM; output never occupies L2 ways, no end-of-kernel drain
                __stwt(reinterpret_cast<float4*>(ob + (size_t)lr * D_), acc);
            }
        }
    }
}

extern "C" void kernel_launch(void* const* d_in, const int* in_sizes, int n_in,
                              void* d_out, int out_size)
{
    const float* x    = (const float*)d_in[0];  // (B,L,D)
    const float* sb   = (const float*)d_in[1];  // (B,L)
    const float* w    = (const float*)d_in[2];  // (D,1,K)
    const float* bias = (const float*)d_in[3];  // (D,)
    float* out        = (float*)d_out;          // (B,L,D)

    dwconv_pipe_kernel<<<B_ * STRIPS_, THREADS_>>>(x, sb, w, bias, out);
}

// round 16
// speedup vs baseline: 1.0007x; 1.0007x over previous
#include <cuda_runtime.h>

// Problem constants (fixed by the reference)
#define B_       4
#define L_       8192
#define D_       1024
#define K_       7
#define HALF_    3
#define THREADS_ 256      // one float4 (4 channels) per thread: 256*4 = D
#define ROWS_    54       // output rows per strip
#define STRIPS_  152      // ceil(8192/54); grid = 4*152 = 608
#define NSTREAM_ 60       // rows consumed per strip = ROWS_ + K_ - 1
#define PIPE_    10       // smem ring depth (rows); NSTREAM_ % PIPE_ == 0
#define AHEAD_   8        // prefetch distance (< PIPE_ for WAR gap)
#define ROWBYTES_ (THREADS_ * 16)   // 4096 B per ring stage

__global__ __launch_bounds__(THREADS_, 3)
void dwconv_pipe_kernel(const float* __restrict__ x,
                        const float* __restrict__ sb,
                        const float* __restrict__ w,     // (D,1,K) -> w[d*K + k]
                        const float* __restrict__ bias,  // (D,)
                        float* __restrict__ out)
{
    __shared__ __align__(16) float4 ring[PIPE_][THREADS_];
    __shared__ float mask_s[ROWS_];

    const int b  = blockIdx.x / STRIPS_;
    const int j  = blockIdx.x % STRIPS_;
    const int r0 = j * ROWS_;
    const int r1 = min(r0 + ROWS_, L_);
    const int t  = threadIdx.x;

    // ---- masks for strip rows: count boundaries in [l-3,l+3], mask = 2^-cnt
    if (t < ROWS_) {
        const int l = r0 + t;
        float m = 0.0f;
        if (l < L_) {
            float cnt = 0.0f;
            #pragma unroll
            for (int q = -HALF_; q <= HALF_; ++q) {
                const int p = l + q;
                if (p >= 0 && p < L_) cnt += __ldg(sb + b * L_ + p);
            }
            m = exp2f(-cnt);
        }
        mask_s[t] = m;
    }

    // ---- per-thread weights for channels d0..d0+3 (L2-resident)
    const int d0 = t << 2;
    float4 wk[K_];
    #pragma unroll
    for (int k = 0; k < K_; ++k) {
        wk[k].x = __ldg(w + (d0 + 0) * K_ + k);
        wk[k].y = __ldg(w + (d0 + 1) * K_ + k);
        wk[k].z = __ldg(w + (d0 + 2) * K_ + k);
        wk[k].w = __ldg(w + (d0 + 3) * K_ + k);
    }
    const float4 bs = *reinterpret_cast<const float4*>(bias + d0);

    const float* xb = x   + ((size_t)b * L_) * D_ + d0;
    float*       ob = out + ((size_t)b * L_) * D_ + d0;

    const int lr_first = r0 - (K_ - 1);

    const unsigned ring_base =
        (unsigned)__cvta_generic_to_shared(&ring[0][t]);

    // ---- prologue: issue AHEAD_ rows (stages 0..AHEAD_-1), one group each
    #pragma unroll
    for (int s = 0; s < AHEAD_; ++s) {
        const int lr = lr_first + s;
        const int lc = lr < 0 ? 0 : lr;          // clamp; garbage zeroed at use
        const float* src = xb + (size_t)lc * D_;
        asm volatile("cp.async.cg.shared.global [%0], [%1], 16;"
                     :: "r"(ring_base + s * ROWBYTES_), "l"(src));
        asm volatile("cp.async.commit_group;");
    }

    __syncthreads();   // mask_s ready (does not affect per-thread cp.async)

    float4 win[K_];    // filled during first K_-1 iterations (guarded compute)
    #pragma unroll
    for (int k = 0; k < K_; ++k) win[k] = make_float4(0.f, 0.f, 0.f, 0.f);

    #pragma unroll 1
    for (int io = 0; io < NSTREAM_ / PIPE_; ++io) {
        #pragma unroll
        for (int ii = 0; ii < PIPE_; ++ii) {
            const int i  = io * PIPE_ + ii;
            const int lr = lr_first + i;

            // issue prefetch for row i+AHEAD_ (stage (ii+AHEAD_)%PIPE_, static)
            {
                const int ip = i + AHEAD_;
                if (ip < NSTREAM_) {
                    int lrp = lr_first + ip;
                    int lc  = lrp < 0 ? 0 : (lrp >= L_ ? L_ - 1 : lrp);
                    const float* src = xb + (size_t)lc * D_;
                    asm volatile("cp.async.cg.shared.global [%0], [%1], 16;"
                                 :: "r"(ring_base +
                                        ((ii + AHEAD_) % PIPE_) * ROWBYTES_),
                                    "l"(src));
                }
                asm volatile("cp.async.commit_group;");
            }
            // row i complete when at most AHEAD_ groups pending
            asm volatile("cp.async.wait_group %0;" :: "n"(AHEAD_) : "memory");

            // consume row lr (thread reads back only its own 16 B)
            float4 v = ring[ii][t];
            if (lr < 0) v = make_float4(0.f, 0.f, 0.f, 0.f);

            // slide window: win = rows lr-6 .. lr
            #pragma unroll
            for (int k = 0; k < K_ - 1; ++k) win[k] = win[k + 1];
            win[K_ - 1] = v;

            if (lr >= r0 && lr < r1) {
                float4 acc = bs;
                #pragma unroll
                for (int k = 0; k < K_; ++k) {
                    acc.x = fmaf(win[k].x, wk[k].x, acc.x);
                    acc.y = fmaf(win[k].y, wk[k].y, acc.y);
                    acc.z = fmaf(win[k].z, wk[k].z, acc.z);
                    acc.w = fmaf(win[k].w, wk[k].w, acc.w);
                }
                const float m = mask_s[lr - r0];
                acc.x *= m; acc.y *= m; acc.z *= m; acc.w *= m;
                // write-through store: full coalesced 128B lines straight to
                // DRAM; output never occupies L2 ways, no end-of-kernel drain
                __stwt(reinterpret_cast<float4*>(ob + (size_t)lr * D_), acc);
            }
        }
    }
}

extern "C" void kernel_launch(void* const* d_in, const int* in_sizes, int n_in,
                              void* d_out, int out_size)
{
    const float* x    = (const float*)d_in[0];  // (B,L,D)
    const float* sb   = (const float*)d_in[1];  // (B,L)
    const float* w    = (const float*)d_in[2];  // (D,1,K)
    const float* bias = (const float*)d_in[3];  // (D,)
    float* out        = (float*)d_out;          // (B,L,D)

    dwconv_pipe_kernel<<<B_ * STRIPS_, THREADS_>>>(x, sb, w, bias, out);
}